// round 2
// baseline (speedup 1.0000x reference)
#include <cuda_runtime.h>
#include <math_constants.h>

// Grayscale morphological erosion, 5x5 SE, 'same' padding, +inf OOB.
// image: (32,3,1024,1024) fp32 -> 96 independent 1024x1024 planes.
//
// Round 2: issue-bound fix.
//  - Each thread computes 4 CONTIGUOUS columns (4*tx..4*tx+3) x 4 rows.
//  - Input window per streamed row = 8 floats = two LDS.128 (conflict-free).
//  - Output stores are STG.128.
//  - Tile 128(W) x 32(H), block (32,8)=256 thr, 4 blocks/SM target.

#define TILE_W 128
#define TILE_H 32
#define RPT 4
#define SW (TILE_W + 4)   // 132 floats = 528 B rows (16B multiple)
#define SH (TILE_H + 4)   // 36

__global__ __launch_bounds__(256, 4)
void erosion5x5_kernel(const float* __restrict__ img,
                       const float* __restrict__ filt,
                       float* __restrict__ out)
{
    __shared__ float s[SH][SW];

    const int tx = threadIdx.x;
    const int ty = threadIdx.y;
    const int tid = ty * 32 + tx;
    const int plane = blockIdx.z;
    const int x0 = blockIdx.x * TILE_W;
    const int y0 = blockIdx.y * TILE_H;

    const float* __restrict__ base = img + (size_t)plane * (1024 * 1024);

    // Structuring element in registers.
    float f[25];
#pragma unroll
    for (int i = 0; i < 25; ++i) f[i] = __ldg(&filt[i]);

    // Cooperative tile fill with +inf border.
    const int total = SH * SW;   // 4752
    for (int idx = tid; idx < total; idx += 256) {
        const int sy = idx / SW;
        const int sx = idx - sy * SW;
        const int gy = y0 + sy - 2;
        const int gx = x0 + sx - 2;
        float v = CUDART_INF_F;
        if ((unsigned)gy < 1024u && (unsigned)gx < 1024u)
            v = __ldg(&base[gy * 1024 + gx]);
        s[sy][sx] = v;
    }
    __syncthreads();

    float acc[RPT][4];
#pragma unroll
    for (int yy = 0; yy < RPT; ++yy)
#pragma unroll
        for (int c = 0; c < 4; ++c)
            acc[yy][c] = CUDART_INF_F;

    const int rbase = ty * RPT;     // this thread's first output row in tile
    const int cbase = tx * 4;       // this thread's first output col in tile

    // Stream the 8 input rows feeding this thread's 4 output rows.
#pragma unroll
    for (int rr = 0; rr < RPT + 4; ++rr) {
        const float4 a = *reinterpret_cast<const float4*>(&s[rbase + rr][cbase]);
        const float4 b = *reinterpret_cast<const float4*>(&s[rbase + rr][cbase + 4]);
        const float w[8] = { a.x, a.y, a.z, a.w, b.x, b.y, b.z, b.w };

#pragma unroll
        for (int yy = 0; yy < RPT; ++yy) {
            const int i = rr - yy;         // SE row index for output row yy
            if (i >= 0 && i < 5) {
#pragma unroll
                for (int c = 0; c < 4; ++c) {
                    float v = acc[yy][c];
                    v = fminf(v, w[c + 0] - f[i * 5 + 0]);
                    v = fminf(v, w[c + 1] - f[i * 5 + 1]);
                    v = fminf(v, w[c + 2] - f[i * 5 + 2]);
                    v = fminf(v, w[c + 3] - f[i * 5 + 3]);
                    v = fminf(v, w[c + 4] - f[i * 5 + 4]);
                    acc[yy][c] = v;
                }
            }
        }
    }

    // Vectorized, coalesced stores. 1024 % 128 == 0 and 1024 % 32 == 0.
    float* __restrict__ obase = out + (size_t)plane * (1024 * 1024);
#pragma unroll
    for (int yy = 0; yy < RPT; ++yy) {
        const int gy = y0 + rbase + yy;
        float4 st;
        st.x = acc[yy][0];
        st.y = acc[yy][1];
        st.z = acc[yy][2];
        st.w = acc[yy][3];
        *reinterpret_cast<float4*>(&obase[(size_t)gy * 1024 + x0 + cbase]) = st;
    }
}

extern "C" void kernel_launch(void* const* d_in, const int* in_sizes, int n_in,
                              void* d_out, int out_size)
{
    const float* img  = (const float*)d_in[0];   // (32,3,1024,1024) fp32
    const float* filt = (const float*)d_in[1];   // (5,5) fp32
    float* out = (float*)d_out;

    dim3 block(32, 8, 1);
    dim3 grid(1024 / TILE_W, 1024 / TILE_H, 32 * 3);
    erosion5x5_kernel<<<grid, block>>>(img, filt, out);
}

// round 3
// speedup vs baseline: 2.9763x; 2.9763x over previous
#include <cuda_runtime.h>
#include <math_constants.h>

// Grayscale morphological erosion, 5x5 SE, 'same' padding, +inf OOB.
// image: (32,3,1024,1024) fp32 -> 96 planes of 1024x1024.
//
// Round 3:
//  - Tile 128(W) x 64(H) per block, block (32,8)=256 thr (R1 geometry).
//  - Shared window origin x0-4, width 136 floats: every float4 is 16B-aligned
//    in gmem and never straddles the image x-border -> pure LDG.128 fill.
//  - Fill is fully unrolled, loads front-batched (MLP=10), then STS.128.
//  - Each thread: 4 CONTIGUOUS cols x 8 rows. Window per streamed row =
//    8 floats = LDS.64 + LDS.128 + LDS.64 (aligned). Stores = STG.128.
//  - Tree-min to shorten acc dependency chains.

#define TILE_W 128
#define TILE_H 64
#define RPT 8
#define SW 136            // TILE_W + 8 (origin x0-4), rows 544B = 16B multiple
#define SH 68             // TILE_H + 4
#define F4_ROW 34         // float4 slots per row
#define FILL_TOTAL (SH * F4_ROW)   // 2312
#define FILL_IT 10                  // ceil(2312/256)

__global__ void erosion5x5_kernel(const float* __restrict__ img,
                                  const float* __restrict__ filt,
                                  float* __restrict__ out)
{
    __shared__ float s[SH][SW];    // 36992 B

    const int tx = threadIdx.x;
    const int ty = threadIdx.y;
    const int tid = ty * 32 + tx;
    const int plane = blockIdx.z;
    const int x0 = blockIdx.x * TILE_W;
    const int y0 = blockIdx.y * TILE_H;

    const float* __restrict__ base = img + (size_t)plane * (1024 * 1024);

    // ---- Fill: front-batched predicated LDG.128, then STS.128 ----
    float4 v[FILL_IT];
    int soff[FILL_IT];
#pragma unroll
    for (int it = 0; it < FILL_IT; ++it) {
        const int idx = tid + it * 256;
        const int sy = idx / F4_ROW;
        const int k  = idx - sy * F4_ROW;
        const int gy = y0 + sy - 2;
        const int gx = x0 + 4 * k - 4;
        // gx % 4 == 0 and borders at 0/1024 -> a float4 is all-in or all-out.
        const bool ok = (idx < FILL_TOTAL) &&
                        ((unsigned)gy < 1024u) && ((unsigned)gx <= 1020u);
        float4 t = make_float4(CUDART_INF_F, CUDART_INF_F,
                               CUDART_INF_F, CUDART_INF_F);
        if (ok)
            t = __ldg(reinterpret_cast<const float4*>(base + (size_t)gy * 1024 + gx));
        v[it] = t;
        soff[it] = sy * SW + 4 * k;
    }
#pragma unroll
    for (int it = 0; it < FILL_IT; ++it) {
        if (it < FILL_IT - 1 || tid + it * 256 < FILL_TOTAL)
            *reinterpret_cast<float4*>(&s[0][0] + soff[it]) = v[it];
    }
    __syncthreads();

    // ---- Structuring element into registers (L2-hot broadcast) ----
    float f[25];
#pragma unroll
    for (int i = 0; i < 25; ++i) f[i] = __ldg(&filt[i]);

    float acc[RPT][4];
#pragma unroll
    for (int yy = 0; yy < RPT; ++yy)
#pragma unroll
        for (int c = 0; c < 4; ++c)
            acc[yy][c] = CUDART_INF_F;

    const int rbase = ty * RPT;    // first output row (tile-local)
    const int cbase = tx * 4;      // first output col (tile-local)

    // ---- Stream 12 input rows feeding this thread's 8 output rows ----
#pragma unroll
    for (int rr = 0; rr < RPT + 4; ++rr) {
        const float* row = &s[rbase + rr][cbase];
        // need smem cols cbase+2 .. cbase+9
        const float2 a = *reinterpret_cast<const float2*>(row + 2); // 8B-aligned
        const float4 b = *reinterpret_cast<const float4*>(row + 4); // 16B-aligned
        const float2 d = *reinterpret_cast<const float2*>(row + 8);
        const float w[8] = { a.x, a.y, b.x, b.y, b.z, b.w, d.x, d.y };

#pragma unroll
        for (int yy = 0; yy < RPT; ++yy) {
            const int i = rr - yy;           // SE row for output row yy
            if (i >= 0 && i < 5) {
#pragma unroll
                for (int c = 0; c < 4; ++c) {
                    const float t0 = fminf(w[c + 0] - f[i * 5 + 0],
                                           w[c + 1] - f[i * 5 + 1]);
                    const float t1 = fminf(w[c + 2] - f[i * 5 + 2],
                                           w[c + 3] - f[i * 5 + 3]);
                    const float t2 = w[c + 4] - f[i * 5 + 4];
                    acc[yy][c] = fminf(acc[yy][c], fminf(t0, fminf(t1, t2)));
                }
            }
        }
    }

    // ---- Vectorized coalesced stores (1024 % 128 == 0, % 64 == 0) ----
    float* __restrict__ obase = out + (size_t)plane * (1024 * 1024);
#pragma unroll
    for (int yy = 0; yy < RPT; ++yy) {
        const int gy = y0 + rbase + yy;
        float4 st;
        st.x = acc[yy][0];
        st.y = acc[yy][1];
        st.z = acc[yy][2];
        st.w = acc[yy][3];
        *reinterpret_cast<float4*>(&obase[(size_t)gy * 1024 + x0 + cbase]) = st;
    }
}

extern "C" void kernel_launch(void* const* d_in, const int* in_sizes, int n_in,
                              void* d_out, int out_size)
{
    const float* img  = (const float*)d_in[0];   // (32,3,1024,1024) fp32
    const float* filt = (const float*)d_in[1];   // (5,5) fp32
    float* out = (float*)d_out;

    dim3 block(32, 8, 1);
    dim3 grid(1024 / TILE_W, 1024 / TILE_H, 32 * 3);
    erosion5x5_kernel<<<grid, block>>>(img, filt, out);
}